// round 10
// baseline (speedup 1.0000x reference)
#include <cuda_runtime.h>

// out[b,pi,pj,h,w] = leaky_relu( (1/32) * sum_c x1[b,c,h,w] *
//                    x2_pad[b,c, h+2*pi-20, w+2*pj-20], 0.1 )
// B=4, C=32, H=32, W=1024, PATCH=21, DIL=2, PAD=20.
// Persistent-CTA schedule: 592 blocks (148 SM x 4 resident), each owns a
// contiguous run of items; item = (tile, pi-quarter). Same tile across items
// -> x1 stays staged. R9 compute loop + bulk/mbarrier staging unchanged.

#define WT      128
#define SLICE   168
#define CPH     4
#define NBUF    2
#define BUF_FLOATS (CPH * SLICE)   // 672
#define NBLOCKS 592
#define NITEMS  4096               // 1024 tiles * 4 quarters

__device__ __forceinline__ unsigned long long ffma2(unsigned long long a,
                                                    unsigned long long b,
                                                    unsigned long long c) {
    unsigned long long d;
    asm("fma.rn.f32x2 %0, %1, %2, %3;" : "=l"(d) : "l"(a), "l"(b), "l"(c));
    return d;
}

__device__ __forceinline__ void mbar_init(unsigned mb) {
    asm volatile("mbarrier.init.shared.b64 [%0], 1;" :: "r"(mb) : "memory");
}
__device__ __forceinline__ void mbar_expect(unsigned mb, unsigned bytes) {
    asm volatile("mbarrier.arrive.expect_tx.shared.b64 _, [%0], %1;"
                 :: "r"(mb), "r"(bytes) : "memory");
}
__device__ __forceinline__ void bulk_g2s(unsigned dst, const void* src,
                                         unsigned bytes, unsigned mb) {
    asm volatile(
        "cp.async.bulk.shared::cta.global.mbarrier::complete_tx::bytes "
        "[%0], [%1], %2, [%3];"
        :: "r"(dst), "l"(src), "r"(bytes), "r"(mb) : "memory");
}
__device__ __forceinline__ void mbar_wait(unsigned mb, unsigned phase) {
    asm volatile(
        "{\n\t"
        ".reg .pred P;\n\t"
        "LAB_WAIT_%=:\n\t"
        "mbarrier.try_wait.parity.acquire.cta.shared::cta.b64 P, [%0], %1, 0x989680;\n\t"
        "@P bra.uni LAB_DONE_%=;\n\t"
        "bra.uni LAB_WAIT_%=;\n\t"
        "LAB_DONE_%=:\n\t"
        "}"
        :: "r"(mb), "r"(phase) : "memory");
}

extern __shared__ float smem[];

__global__ void __launch_bounds__(128, 4)
corr_kernel(const float* __restrict__ x1, const float* __restrict__ x2,
            float* __restrict__ out)
{
    const int tid  = threadIdx.x;
    const int wid  = tid >> 5;
    const int lane = tid & 31;
    const int g    = lane >> 1;         // 16 w-groups of 8 w's
    const int half = lane & 1;          // 0: pj 0..10, 1: pj 10..20

    float* x1s = smem;                                       // [32][WT]
    float* x2b = smem + 32 * WT + wid * (NBUF * BUF_FLOATS);

    const unsigned smem_b  = (unsigned)__cvta_generic_to_shared(smem);
    const unsigned mb_base = smem_b +
        (unsigned)(32 * WT + 4 * NBUF * BUF_FLOATS) * 4u + (unsigned)wid * 16u;

    if (tid < 4) { }  // (keep layout simple)
    if (lane == 0) { mbar_init(mb_base); mbar_init(mb_base + 8); }

    // contiguous item range for this block
    const int i0 = (int)(((long long)blockIdx.x       * NITEMS) / NBLOCKS);
    const int i1 = (int)(((long long)(blockIdx.x + 1) * NITEMS) / NBLOCKS);

    // per-tile state (updated on tile change)
    int b = 0, h = 0, w0 = 0, prev_tile = -1;
    int srcw = 0, lo = 0, hi = SLICE;
    unsigned cpb = 0;

    // quarter tables: pi in [qs, qs+qn)
    const int qs_tab[4] = {0, 6, 11, 16};
    const int qn_tab[4] = {6, 5, 5, 5};

    unsigned long long acc[11][4];
    #pragma unroll
    for (int p = 0; p < 11; p++)
        #pragma unroll
        for (int q = 0; q < 4; q++) acc[p][q] = 0ull;

    const float sp = 0.03125f;    // 1/32
    const float sn = 0.003125f;   // 0.1/32
    unsigned pb0 = 0, pb1 = 0;    // consumer phase bits per buffer

    __syncthreads();              // mbarrier init visible block-wide

    for (int it = i0; it < i1; it++) {
        const int tile = it >> 2;
        const int qt   = it & 3;

        if (tile != prev_tile) {
            prev_tile = tile;
            b  = tile >> 8;
            h  = (tile >> 3) & 31;
            w0 = (tile & 7) * WT;

            __syncthreads();      // all warps done with old x1
            for (int f = tid; f < 32 * (WT / 4); f += 128) {
                const int c = f >> 5;
                const int j = f & 31;
                reinterpret_cast<float4*>(x1s)[f] =
                    *reinterpret_cast<const float4*>(
                        x1 + ((size_t)(b * 32 + c) * 32 + h) * 1024 + w0 + 4 * j);
            }
            __syncthreads();

            srcw = (w0 >= 20) ? (w0 - 20) : 0;
            lo   = (w0 >= 20) ? 0 : (20 - w0);
            hi   = (1044 - w0 < SLICE) ? (1044 - w0) : SLICE;
            cpb  = (unsigned)(hi - lo) * 4u;

            if (lo > 0 || hi < SLICE) {       // zero margins (pipeline drained)
                const float4 z = make_float4(0.f, 0.f, 0.f, 0.f);
                for (int j = lane; j < NBUF * BUF_FLOATS / 4; j += 32)
                    reinterpret_cast<float4*>(x2b)[j] = z;
            }
            __syncwarp();
        }

        const int qs  = qs_tab[qt];
        const int qn  = qn_tab[qt];
        const int npi = (wid < qn) ? ((qn - 1 - wid) >> 2) + 1 : 0;
        const int total = npi * 8;
        if (total == 0) continue;

        auto do_stage = [&](int s) {
            const int pi = qs + wid + ((s >> 3) << 2);
            const int h2 = h + 2 * pi - 20;
            float* dst = x2b + (s & 1) * BUF_FLOATS;
            if ((unsigned)h2 < 32u) {
                if (lane == 0) {
                    const int ph = s & 7;
                    const unsigned mb = mb_base + (unsigned)(s & 1) * 8u;
                    mbar_expect(mb, cpb * CPH);
                    const float* src =
                        x2 + ((size_t)(b * 32 + ph * CPH) * 32 + h2) * 1024 + srcw;
                    const unsigned d =
                        smem_b + (unsigned)((int)(dst - smem) + lo) * 4u;
                    #pragma unroll
                    for (int r = 0; r < CPH; r++)
                        bulk_g2s(d + (unsigned)r * (SLICE * 4u),
                                 src + (size_t)r * 32 * 1024, cpb, mb);
                }
            } else {
                const float4 z = make_float4(0.f, 0.f, 0.f, 0.f);
                for (int j = lane; j < BUF_FLOATS / 4; j += 32)
                    reinterpret_cast<float4*>(dst)[j] = z;
            }
        };

        const float* x1base = x1s + 8 * g;

        do_stage(0);

        for (int s = 0; s < total; s++) {
            if (s + 1 < total) do_stage(s + 1);

            {   // consume stage s
                const int pi = qs + wid + ((s >> 3) << 2);
                const int h2 = h + 2 * pi - 20;
                if ((unsigned)h2 < 32u) {
                    if ((s & 1) == 0) { mbar_wait(mb_base,     pb0); pb0 ^= 1; }
                    else              { mbar_wait(mb_base + 8, pb1); pb1 ^= 1; }
                }
            }
            __syncwarp();

            const float* buf = x2b + (s & 1) * BUF_FLOATS;
            const int ph = s & 7;
            const float* x1p = x1base + ph * CPH * WT;
            const float* xwp = buf + 8 * g + 20 * half;

            #pragma unroll 2
            for (int c = 0; c < CPH; c++) {
                const float* x1row = x1p + c * WT;
                const ulonglong2 A0 = *reinterpret_cast<const ulonglong2*>(x1row);
                const ulonglong2 A1 = *reinterpret_cast<const ulonglong2*>(x1row + 4);
                const unsigned long long a[4] = {A0.x, A0.y, A1.x, A1.y};

                ulonglong2 X[7];
                const float* bp = xwp + c * SLICE;
                #pragma unroll
                for (int j = 0; j < 7; j++)
                    X[j] = *reinterpret_cast<const ulonglong2*>(bp + 4 * j);

                #pragma unroll
                for (int p = 0; p < 11; p++) {
                    #pragma unroll
                    for (int q = 0; q < 4; q++) {
                        const int k = p + q;                       // 0..13
                        const unsigned long long pk = (k & 1) ? X[k >> 1].y
                                                              : X[k >> 1].x;
                        acc[p][q] = ffma2(a[q], pk, acc[p][q]);
                    }
                }
            }

            if ((s & 7) == 7) {   // per-pi epilogue
                const int pi = qs + wid + ((s >> 3) << 2);
                #pragma unroll
                for (int p = 0; p < 11; p++) {
                    if (!(half == 1 && p == 0)) {  // pj=10 dup by half A
                        const int pj = half ? (p + 10) : p;
                        float* op = out +
                            (((size_t)b * 441 + pi * 21 + pj) * 32 + h) * 1024 +
                            w0 + 8 * g;
                        float v[8];
                        #pragma unroll
                        for (int q = 0; q < 4; q++) {
                            float2 fv = *reinterpret_cast<float2*>(&acc[p][q]);
                            v[2 * q]     = fv.x * ((fv.x < 0.f) ? sn : sp);
                            v[2 * q + 1] = fv.y * ((fv.y < 0.f) ? sn : sp);
                        }
                        *reinterpret_cast<float4*>(op) =
                            make_float4(v[0], v[1], v[2], v[3]);
                        *reinterpret_cast<float4*>(op + 4) =
                            make_float4(v[4], v[5], v[6], v[7]);
                    }
                    #pragma unroll
                    for (int q = 0; q < 4; q++) acc[p][q] = 0ull;
                }
            }
            __syncwarp();   // buffer reads done before restage
        }
    }
}

extern "C" void kernel_launch(void* const* d_in, const int* in_sizes, int n_in,
                              void* d_out, int out_size) {
    const float* x1 = (const float*)d_in[0];
    const float* x2 = (const float*)d_in[1];
    float* out = (float*)d_out;

    const size_t smem_bytes =
        (size_t)(32 * WT + 4 * NBUF * BUF_FLOATS) * sizeof(float) + 64;  // 37952 B
    cudaFuncSetAttribute(corr_kernel,
                         cudaFuncAttributeMaxDynamicSharedMemorySize,
                         (int)smem_bytes);

    corr_kernel<<<NBLOCKS, 128, smem_bytes>>>(x1, x2, out);
}

// round 11
// speedup vs baseline: 1.7222x; 1.7222x over previous
#include <cuda_runtime.h>

// out[b,pi,pj,h,w] = leaky_relu( (1/32) * sum_c x1[b,c,h,w] *
//                    x2_pad[b,c, h+2*pi-20, w+2*pj-20], 0.1 )
// B=4, C=32, H=32, W=1024, PATCH=21, DIL=2, PAD=20.
// R9 pipeline + h2-validity skip: out-of-range (h,pi) rows are exactly zero
// (leaky_relu(0)=0), so they get zero-stores only — no LDS/FMA. That removes
// ~33% of all compute work.

#define WT      128
#define SLICE   168
#define CPH     4
#define NBUF    2
#define BUF_FLOATS (CPH * SLICE)   // 672

__device__ __forceinline__ unsigned long long ffma2(unsigned long long a,
                                                    unsigned long long b,
                                                    unsigned long long c) {
    unsigned long long d;
    asm("fma.rn.f32x2 %0, %1, %2, %3;" : "=l"(d) : "l"(a), "l"(b), "l"(c));
    return d;
}

__device__ __forceinline__ void mbar_init(unsigned mb) {
    asm volatile("mbarrier.init.shared.b64 [%0], 1;" :: "r"(mb) : "memory");
}
__device__ __forceinline__ void mbar_expect(unsigned mb, unsigned bytes) {
    asm volatile("mbarrier.arrive.expect_tx.shared.b64 _, [%0], %1;"
                 :: "r"(mb), "r"(bytes) : "memory");
}
__device__ __forceinline__ void bulk_g2s(unsigned dst, const void* src,
                                         unsigned bytes, unsigned mb) {
    asm volatile(
        "cp.async.bulk.shared::cta.global.mbarrier::complete_tx::bytes "
        "[%0], [%1], %2, [%3];"
        :: "r"(dst), "l"(src), "r"(bytes), "r"(mb) : "memory");
}
__device__ __forceinline__ void mbar_wait(unsigned mb, unsigned phase) {
    asm volatile(
        "{\n\t"
        ".reg .pred P;\n\t"
        "LAB_WAIT_%=:\n\t"
        "mbarrier.try_wait.parity.acquire.cta.shared::cta.b64 P, [%0], %1, 0x989680;\n\t"
        "@P bra.uni LAB_DONE_%=;\n\t"
        "bra.uni LAB_WAIT_%=;\n\t"
        "LAB_DONE_%=:\n\t"
        "}"
        :: "r"(mb), "r"(phase) : "memory");
}

extern __shared__ float smem[];

__global__ void __launch_bounds__(128, 4)
corr_kernel(const float* __restrict__ x1, const float* __restrict__ x2,
            float* __restrict__ out)
{
    const int w0   = blockIdx.x * WT;
    const int h    = blockIdx.y;
    const int b    = blockIdx.z;
    const int tid  = threadIdx.x;
    const int wid  = tid >> 5;          // 4 warps
    const int lane = tid & 31;
    const int g    = lane >> 1;         // 16 w-groups of 8 w's
    const int half = lane & 1;          // 0: pj 0..10, 1: pj 10..20

    float* x1s = smem;                                       // [32][WT]
    float* x2b = smem + 32 * WT + wid * (NBUF * BUF_FLOATS);

    const unsigned smem_b  = (unsigned)__cvta_generic_to_shared(smem);
    const unsigned mb_base = smem_b +
        (unsigned)(32 * WT + 4 * NBUF * BUF_FLOATS) * 4u + (unsigned)wid * 16u;

    // ---- stage x1 tile: 32 channels x WT floats ----
    for (int f = tid; f < 32 * (WT / 4); f += 128) {
        const int c = f >> 5;
        const int j = f & 31;
        reinterpret_cast<float4*>(x1s)[f] = *reinterpret_cast<const float4*>(
            x1 + ((size_t)(b * 32 + c) * 32 + h) * 1024 + w0 + 4 * j);
    }
    __syncthreads();

    // per-block bulk-copy clipping (fixed for all stages)
    const int srcw = (w0 >= 20) ? (w0 - 20) : 0;
    const int lo   = (w0 >= 20) ? 0 : (20 - w0);
    const int hi   = (1044 - w0 < SLICE) ? (1044 - w0) : SLICE;
    const unsigned cpb = (unsigned)(hi - lo) * 4u;

    if (lane == 0) { mbar_init(mb_base); mbar_init(mb_base + 8); }
    if (lo > 0 || hi < SLICE) {                 // zero margins once
        const float4 z = make_float4(0.f, 0.f, 0.f, 0.f);
        for (int j = lane; j < NBUF * BUF_FLOATS / 4; j += 32)
            reinterpret_cast<float4*>(x2b)[j] = z;
    }
    __syncwarp();

    // valid pi range for this h: h2 = h + 2*pi - 20 in [0,32)
    const int pi_lo = (h >= 21) ? 0 : ((21 - h) >> 1);
    const int pi_hi = ((51 - h) >> 1) < 20 ? ((51 - h) >> 1) : 20;
    // warp handles pi = wid + 4k, k in [0, kmax]; valid k in [k0, k1]
    const int kmax = (20 - wid) >> 2;
    const int k0   = (pi_lo > wid) ? ((pi_lo - wid + 3) >> 2) : 0;
    const int k1   = (pi_hi - wid) >> 2;        // pi_hi >= 10 >= wid always
    const int nval = k1 - k0 + 1;               // >= 1 (range length >= 11)
    const int total = nval * 8;

    // acc[p][q]: pj = p + 10*half, w-pair q of this lane's 8 w's
    unsigned long long acc[11][4];
    #pragma unroll
    for (int p = 0; p < 11; p++)
        #pragma unroll
        for (int q = 0; q < 4; q++) acc[p][q] = 0ull;

    const float* x1base = x1s + 8 * g;
    const float sp = 0.03125f;    // 1/32
    const float sn = 0.003125f;   // 0.1/32
    unsigned pb0 = 0, pb1 = 0;

    auto do_stage = [&](int s) {
        if (lane == 0) {
            const int pi = wid + ((k0 + (s >> 3)) << 2);
            const int h2 = h + 2 * pi - 20;     // always valid here
            const int ph = s & 7;
            const unsigned mb = mb_base + (unsigned)(s & 1) * 8u;
            mbar_expect(mb, cpb * CPH);
            const float* src =
                x2 + ((size_t)(b * 32 + ph * CPH) * 32 + h2) * 1024 + srcw;
            const unsigned d = smem_b +
                (unsigned)(32 * WT + wid * (NBUF * BUF_FLOATS) +
                           (s & 1) * BUF_FLOATS + lo) * 4u;
            #pragma unroll
            for (int r = 0; r < CPH; r++)
                bulk_g2s(d + (unsigned)r * (SLICE * 4u),
                         src + (size_t)r * 32 * 1024, cpb, mb);
        }
    };

    do_stage(0);

    for (int s = 0; s < total; s++) {
        if (s + 1 < total) do_stage(s + 1);

        if ((s & 1) == 0) { mbar_wait(mb_base,     pb0); pb0 ^= 1; }
        else              { mbar_wait(mb_base + 8, pb1); pb1 ^= 1; }
        __syncwarp();

        // ---- compute stage s: 4 channels ----
        const float* buf = x2b + (s & 1) * BUF_FLOATS;
        const int ph = s & 7;
        const float* x1p = x1base + ph * CPH * WT;
        const float* xwp = buf + 8 * g + 20 * half;

        #pragma unroll 2
        for (int c = 0; c < CPH; c++) {
            const float* x1row = x1p + c * WT;
            const ulonglong2 A0 = *reinterpret_cast<const ulonglong2*>(x1row);
            const ulonglong2 A1 = *reinterpret_cast<const ulonglong2*>(x1row + 4);
            const unsigned long long a[4] = {A0.x, A0.y, A1.x, A1.y};

            ulonglong2 X[7];
            const float* bp = xwp + c * SLICE;
            #pragma unroll
            for (int j = 0; j < 7; j++)
                X[j] = *reinterpret_cast<const ulonglong2*>(bp + 4 * j);

            #pragma unroll
            for (int p = 0; p < 11; p++) {
                #pragma unroll
                for (int q = 0; q < 4; q++) {
                    const int k = p + q;                       // 0..13
                    const unsigned long long pk = (k & 1) ? X[k >> 1].y
                                                          : X[k >> 1].x;
                    acc[p][q] = ffma2(a[q], pk, acc[p][q]);
                }
            }
        }

        // ---- per-pi epilogue after last phase ----
        if ((s & 7) == 7) {
            const int pi = wid + ((k0 + (s >> 3)) << 2);
            #pragma unroll
            for (int p = 0; p < 11; p++) {
                if (!(half == 1 && p == 0)) {      // pj=10 dup by half A
                    const int pj = half ? (p + 10) : p;
                    float* op = out +
                        (((size_t)b * 441 + pi * 21 + pj) * 32 + h) * 1024 +
                        w0 + 8 * g;
                    float v[8];
                    #pragma unroll
                    for (int q = 0; q < 4; q++) {
                        float2 fv = *reinterpret_cast<float2*>(&acc[p][q]);
                        v[2 * q]     = fv.x * ((fv.x < 0.f) ? sn : sp);
                        v[2 * q + 1] = fv.y * ((fv.y < 0.f) ? sn : sp);
                    }
                    *reinterpret_cast<float4*>(op) =
                        make_float4(v[0], v[1], v[2], v[3]);
                    *reinterpret_cast<float4*>(op + 4) =
                        make_float4(v[4], v[5], v[6], v[7]);
                }
                #pragma unroll
                for (int q = 0; q < 4; q++) acc[p][q] = 0ull;
            }
        }
        __syncwarp();   // buffer reads done before restage
    }

    // ---- zero-store epilogue for out-of-range pi (h2 invalid -> out = 0) ----
    {
        const float4 z = make_float4(0.f, 0.f, 0.f, 0.f);
        for (int k = 0; k <= kmax; k++) {
            if (k >= k0 && k <= k1) continue;
            const int pi = wid + (k << 2);
            #pragma unroll
            for (int p = 0; p < 11; p++) {
                if (half == 1 && p == 0) continue;
                const int pj = half ? (p + 10) : p;
                float* op = out +
                    (((size_t)b * 441 + pi * 21 + pj) * 32 + h) * 1024 +
                    w0 + 8 * g;
                *reinterpret_cast<float4*>(op)     = z;
                *reinterpret_cast<float4*>(op + 4) = z;
            }
        }
    }
}

extern "C" void kernel_launch(void* const* d_in, const int* in_sizes, int n_in,
                              void* d_out, int out_size) {
    const float* x1 = (const float*)d_in[0];
    const float* x2 = (const float*)d_in[1];
    float* out = (float*)d_out;

    const size_t smem_bytes =
        (size_t)(32 * WT + 4 * NBUF * BUF_FLOATS) * sizeof(float) + 64;  // 37952 B
    cudaFuncSetAttribute(corr_kernel,
                         cudaFuncAttributeMaxDynamicSharedMemorySize,
                         (int)smem_bytes);

    dim3 grid(1024 / WT, 32, 4);   // (w-tiles, H, B)
    corr_kernel<<<grid, 128, smem_bytes>>>(x1, x2, out);
}

// round 13
// speedup vs baseline: 1.7227x; 1.0003x over previous
#include <cuda_runtime.h>

// out[b,pi,pj,h,w] = leaky_relu( (1/32) * sum_c x1[b,c,h,w] *
//                    x2_pad[b,c, h+2*pi-20, w+2*pj-20], 0.1 )
// B=4, C=32, H=32, W=1024, PATCH=21, DIL=2, PAD=20.
// R11 + triple-buffered bulk pipeline (prefetch distance 2) and no per-stage
// __syncwarp. Out-of-range (h,pi) rows skipped (exact zeros).

#define WT      128
#define SLICE   168
#define CPH     4
#define NBUF    3
#define BUF_FLOATS (CPH * SLICE)   // 672

__device__ __forceinline__ unsigned long long ffma2(unsigned long long a,
                                                    unsigned long long b,
                                                    unsigned long long c) {
    unsigned long long d;
    asm("fma.rn.f32x2 %0, %1, %2, %3;" : "=l"(d) : "l"(a), "l"(b), "l"(c));
    return d;
}

__device__ __forceinline__ void mbar_init(unsigned mb) {
    asm volatile("mbarrier.init.shared.b64 [%0], 1;" :: "r"(mb) : "memory");
}
__device__ __forceinline__ void mbar_expect(unsigned mb, unsigned bytes) {
    asm volatile("mbarrier.arrive.expect_tx.shared.b64 _, [%0], %1;"
                 :: "r"(mb), "r"(bytes) : "memory");
}
__device__ __forceinline__ void bulk_g2s(unsigned dst, const void* src,
                                         unsigned bytes, unsigned mb) {
    asm volatile(
        "cp.async.bulk.shared::cta.global.mbarrier::complete_tx::bytes "
        "[%0], [%1], %2, [%3];"
        :: "r"(dst), "l"(src), "r"(bytes), "r"(mb) : "memory");
}
__device__ __forceinline__ void mbar_wait(unsigned mb, unsigned phase) {
    asm volatile(
        "{\n\t"
        ".reg .pred P;\n\t"
        "LAB_WAIT_%=:\n\t"
        "mbarrier.try_wait.parity.acquire.cta.shared::cta.b64 P, [%0], %1, 0x989680;\n\t"
        "@P bra.uni LAB_DONE_%=;\n\t"
        "bra.uni LAB_WAIT_%=;\n\t"
        "LAB_DONE_%=:\n\t"
        "}"
        :: "r"(mb), "r"(phase) : "memory");
}

extern __shared__ float smem[];

__global__ void __launch_bounds__(128, 4)
corr_kernel(const float* __restrict__ x1, const float* __restrict__ x2,
            float* __restrict__ out)
{
    const int w0   = blockIdx.x * WT;
    const int h    = blockIdx.y;
    const int b    = blockIdx.z;
    const int tid  = threadIdx.x;
    const int wid  = tid >> 5;          // 4 warps
    const int lane = tid & 31;
    const int g    = lane >> 1;         // 16 w-groups of 8 w's
    const int half = lane & 1;          // 0: pj 0..10, 1: pj 10..20

    float* x1s = smem;                                       // [32][WT]
    float* x2b = smem + 32 * WT + wid * (NBUF * BUF_FLOATS);

    const unsigned smem_b  = (unsigned)__cvta_generic_to_shared(smem);
    const unsigned mb_base = smem_b +
        (unsigned)(32 * WT + 4 * NBUF * BUF_FLOATS) * 4u + (unsigned)wid * 24u;
    // mbarriers: 3 per warp (one per buffer)

    // ---- stage x1 tile: 32 channels x WT floats ----
    for (int f = tid; f < 32 * (WT / 4); f += 128) {
        const int c = f >> 5;
        const int j = f & 31;
        reinterpret_cast<float4*>(x1s)[f] = *reinterpret_cast<const float4*>(
            x1 + ((size_t)(b * 32 + c) * 32 + h) * 1024 + w0 + 4 * j);
    }
    __syncthreads();

    // per-block bulk-copy clipping (fixed for all stages)
    const int srcw = (w0 >= 20) ? (w0 - 20) : 0;
    const int lo   = (w0 >= 20) ? 0 : (20 - w0);
    const int hi   = (1044 - w0 < SLICE) ? (1044 - w0) : SLICE;
    const unsigned cpb = (unsigned)(hi - lo) * 4u;

    if (lane == 0) {
        mbar_init(mb_base);
        mbar_init(mb_base + 8);
        mbar_init(mb_base + 16);
    }
    if (lo > 0 || hi < SLICE) {                 // zero margins once
        const float4 z = make_float4(0.f, 0.f, 0.f, 0.f);
        for (int j = lane; j < NBUF * BUF_FLOATS / 4; j += 32)
            reinterpret_cast<float4*>(x2b)[j] = z;
    }
    __syncwarp();   // zeroed margins + mbarrier init visible warp-wide

    // valid pi range for this h: h2 = h + 2*pi - 20 in [0,32)
    const int pi_lo = (h >= 21) ? 0 : ((21 - h) >> 1);
    const int pi_hi = ((51 - h) >> 1) < 20 ? ((51 - h) >> 1) : 20;
    const int kmax = (20 - wid) >> 2;
    const int k0   = (pi_lo > wid) ? ((pi_lo - wid + 3) >> 2) : 0;
    const int k1   = (pi_hi - wid) >> 2;
    const int nval = k1 - k0 + 1;               // >= 2 always (range >= 11)
    const int total = nval * 8;

    // acc[p][q]: pj = p + 10*half, w-pair q of this lane's 8 w's
    unsigned long long acc[11][4];
    #pragma unroll
    for (int p = 0; p < 11; p++)
        #pragma unroll
        for (int q = 0; q < 4; q++) acc[p][q] = 0ull;

    const float* x1base = x1s + 8 * g;
    const float sp = 0.03125f;    // 1/32
    const float sn = 0.003125f;   // 0.1/32

    auto do_stage = [&](int s) {
        if (lane == 0) {
            const int bi = s - 3 * (s / 3);     // s % 3
            const int pi = wid + ((k0 + (s >> 3)) << 2);
            const int h2 = h + 2 * pi - 20;     // always valid
            const int ph = s & 7;
            const unsigned mb = mb_base + (unsigned)bi * 8u;
            mbar_expect(mb, cpb * CPH);
            const float* src =
                x2 + ((size_t)(b * 32 + ph * CPH) * 32 + h2) * 1024 + srcw;
            const unsigned d = smem_b +
                (unsigned)(32 * WT + wid * (NBUF * BUF_FLOATS) +
                           bi * BUF_FLOATS + lo) * 4u;
            #pragma unroll
            for (int r = 0; r < CPH; r++)
                bulk_g2s(d + (unsigned)r * (SLICE * 4u),
                         src + (size_t)r * 32 * 1024, cpb, mb);
        }
    };

    do_stage(0);
    do_stage(1);    // total >= 16 always

    for (int s = 0; s < total; s++) {
        if (s + 2 < total) do_stage(s + 2);

        const int sdiv3 = s / 3;
        const int bi    = s - 3 * sdiv3;
        mbar_wait(mb_base + (unsigned)bi * 8u, (unsigned)(sdiv3 & 1));

        // ---- compute stage s: 4 channels ----
        const float* buf = x2b + bi * BUF_FLOATS;
        const int ph = s & 7;
        const float* x1p = x1base + ph * CPH * WT;
        const float* xwp = buf + 8 * g + 20 * half;

        #pragma unroll 2
        for (int c = 0; c < CPH; c++) {
            const float* x1row = x1p + c * WT;
            const ulonglong2 A0 = *reinterpret_cast<const ulonglong2*>(x1row);
            const ulonglong2 A1 = *reinterpret_cast<const ulonglong2*>(x1row + 4);
            const unsigned long long a[4] = {A0.x, A0.y, A1.x, A1.y};

            ulonglong2 X[7];
            const float* bp = xwp + c * SLICE;
            #pragma unroll
            for (int j = 0; j < 7; j++)
                X[j] = *reinterpret_cast<const ulonglong2*>(bp + 4 * j);

            #pragma unroll
            for (int p = 0; p < 11; p++) {
                #pragma unroll
                for (int q = 0; q < 4; q++) {
                    const int k = p + q;                       // 0..13
                    const unsigned long long pk = (k & 1) ? X[k >> 1].y
                                                          : X[k >> 1].x;
                    acc[p][q] = ffma2(a[q], pk, acc[p][q]);
                }
            }
        }

        // ---- per-pi epilogue after last phase ----
        if ((s & 7) == 7) {
            const int pi = wid + ((k0 + (s >> 3)) << 2);
            #pragma unroll
            for (int p = 0; p < 11; p++) {
                if (!(half == 1 && p == 0)) {      // pj=10 dup by half A
                    const int pj = half ? (p + 10) : p;
                    float* op = out +
                        (((size_t)b * 441 + pi * 21 + pj) * 32 + h) * 1024 +
                        w0 + 8 * g;
                    float v[8];
                    #pragma unroll
                    for (int q = 0; q < 4; q++) {
                        float2 fv = *reinterpret_cast<float2*>(&acc[p][q]);
                        v[2 * q]     = fv.x * ((fv.x < 0.f) ? sn : sp);
                        v[2 * q + 1] = fv.y * ((fv.y < 0.f) ? sn : sp);
                    }
                    *reinterpret_cast<float4*>(op) =
                        make_float4(v[0], v[1], v[2], v[3]);
                    *reinterpret_cast<float4*>(op + 4) =
                        make_float4(v[4], v[5], v[6], v[7]);
                }
                #pragma unroll
                for (int q = 0; q < 4; q++) acc[p][q] = 0ull;
            }
        }
    }

    // ---- zero-store epilogue for out-of-range pi (h2 invalid -> out = 0) ----
    {
        const float4 z = make_float4(0.f, 0.f, 0.f, 0.f);
        for (int k = 0; k <= kmax; k++) {
            if (k >= k0 && k <= k1) continue;
            const int pi = wid + (k << 2);
            #pragma unroll
            for (int p = 0; p < 11; p++) {
                if (half == 1 && p == 0) continue;
                const int pj = half ? (p + 10) : p;
                float* op = out +
                    (((size_t)b * 441 + pi * 21 + pj) * 32 + h) * 1024 +
                    w0 + 8 * g;
                *reinterpret_cast<float4*>(op)     = z;
                *reinterpret_cast<float4*>(op + 4) = z;
            }
        }
    }
}

extern "C" void kernel_launch(void* const* d_in, const int* in_sizes, int n_in,
                              void* d_out, int out_size) {
    const float* x1 = (const float*)d_in[0];
    const float* x2 = (const float*)d_in[1];
    float* out = (float*)d_out;

    // x1 tile + 4 warps * 3 buffers * 672 floats + 12 mbarriers
    const size_t smem_bytes =
        (size_t)(32 * WT + 4 * NBUF * BUF_FLOATS) * sizeof(float) + 96;  // 48736 B
    cudaFuncSetAttribute(corr_kernel,
                         cudaFuncAttributeMaxDynamicSharedMemorySize,
                         (int)smem_bytes);

    dim3 grid(1024 / WT, 32, 4);   // (w-tiles, H, B)
    corr_kernel<<<grid, 128, smem_bytes>>>(x1, x2, out);
}

// round 14
// speedup vs baseline: 1.7668x; 1.0256x over previous
#include <cuda_runtime.h>

// out[b,pi,pj,h,w] = leaky_relu( (1/32) * sum_c x1[b,c,h,w] *
//                    x2_pad[b,c, h+2*pi-20, w+2*pj-20], 0.1 )
// B=4, C=32, H=32, W=1024, PATCH=21, DIL=2, PAD=20.
// Double-buffered bulk pipeline, sync-free stage loop, validity skip,
// incremental per-stage pointer arithmetic.

#define WT      128
#define SLICE   168
#define CPH     4
#define NBUF    2
#define BUF_FLOATS (CPH * SLICE)   // 672

__device__ __forceinline__ unsigned long long ffma2(unsigned long long a,
                                                    unsigned long long b,
                                                    unsigned long long c) {
    unsigned long long d;
    asm("fma.rn.f32x2 %0, %1, %2, %3;" : "=l"(d) : "l"(a), "l"(b), "l"(c));
    return d;
}

__device__ __forceinline__ void mbar_init(unsigned mb) {
    asm volatile("mbarrier.init.shared.b64 [%0], 1;" :: "r"(mb) : "memory");
}
__device__ __forceinline__ void mbar_expect(unsigned mb, unsigned bytes) {
    asm volatile("mbarrier.arrive.expect_tx.shared.b64 _, [%0], %1;"
                 :: "r"(mb), "r"(bytes) : "memory");
}
__device__ __forceinline__ void bulk_g2s(unsigned dst, const void* src,
                                         unsigned bytes, unsigned mb) {
    asm volatile(
        "cp.async.bulk.shared::cta.global.mbarrier::complete_tx::bytes "
        "[%0], [%1], %2, [%3];"
        :: "r"(dst), "l"(src), "r"(bytes), "r"(mb) : "memory");
}
__device__ __forceinline__ void mbar_wait(unsigned mb, unsigned phase) {
    asm volatile(
        "{\n\t"
        ".reg .pred P;\n\t"
        "LAB_WAIT_%=:\n\t"
        "mbarrier.try_wait.parity.acquire.cta.shared::cta.b64 P, [%0], %1, 0x989680;\n\t"
        "@P bra.uni LAB_DONE_%=;\n\t"
        "bra.uni LAB_WAIT_%=;\n\t"
        "LAB_DONE_%=:\n\t"
        "}"
        :: "r"(mb), "r"(phase) : "memory");
}

extern __shared__ float smem[];

__global__ void __launch_bounds__(128, 4)
corr_kernel(const float* __restrict__ x1, const float* __restrict__ x2,
            float* __restrict__ out)
{
    const int w0   = blockIdx.x * WT;
    const int h    = blockIdx.y;
    const int b    = blockIdx.z;
    const int tid  = threadIdx.x;
    const int wid  = tid >> 5;          // 4 warps
    const int lane = tid & 31;
    const int g    = lane >> 1;         // 16 w-groups of 8 w's
    const int half = lane & 1;          // 0: pj 0..10, 1: pj 10..20

    float* x1s = smem;                                       // [32][WT]
    float* x2b = smem + 32 * WT + wid * (NBUF * BUF_FLOATS);

    const unsigned smem_b  = (unsigned)__cvta_generic_to_shared(smem);
    const unsigned mb_base = smem_b +
        (unsigned)(32 * WT + 4 * NBUF * BUF_FLOATS) * 4u + (unsigned)wid * 16u;

    // ---- stage x1 tile: 32 channels x WT floats ----
    for (int f = tid; f < 32 * (WT / 4); f += 128) {
        const int c = f >> 5;
        const int j = f & 31;
        reinterpret_cast<float4*>(x1s)[f] = *reinterpret_cast<const float4*>(
            x1 + ((size_t)(b * 32 + c) * 32 + h) * 1024 + w0 + 4 * j);
    }
    __syncthreads();

    // per-block bulk-copy clipping (fixed for all stages)
    const int srcw = (w0 >= 20) ? (w0 - 20) : 0;
    const int lo   = (w0 >= 20) ? 0 : (20 - w0);
    const int hi   = (1044 - w0 < SLICE) ? (1044 - w0) : SLICE;
    const unsigned cpb = (unsigned)(hi - lo) * 4u;

    if (lane == 0) { mbar_init(mb_base); mbar_init(mb_base + 8); }
    if (lo > 0 || hi < SLICE) {                 // zero margins once
        const float4 z = make_float4(0.f, 0.f, 0.f, 0.f);
        for (int j = lane; j < NBUF * BUF_FLOATS / 4; j += 32)
            reinterpret_cast<float4*>(x2b)[j] = z;
    }
    __syncwarp();   // margins + mbarrier init visible warp-wide

    // valid pi range for this h: h2 = h + 2*pi - 20 in [0,32)
    const int pi_lo = (h >= 21) ? 0 : ((21 - h) >> 1);
    const int pi_hi = ((51 - h) >> 1) < 20 ? ((51 - h) >> 1) : 20;
    const int kmax = (20 - wid) >> 2;
    const int k0   = (pi_lo > wid) ? ((pi_lo - wid + 3) >> 2) : 0;
    const int k1   = (pi_hi - wid) >> 2;
    const int nval = k1 - k0 + 1;               // >= 2 always
    const int total = nval * 8;

    // acc[p][q]: pj = p + 10*half, w-pair q of this lane's 8 w's
    unsigned long long acc[11][4];
    #pragma unroll
    for (int p = 0; p < 11; p++)
        #pragma unroll
        for (int q = 0; q < 4; q++) acc[p][q] = 0ull;

    const float* x1base = x1s + 8 * g;
    const float sp = 0.03125f;    // 1/32
    const float sn = 0.003125f;   // 0.1/32

    // incremental producer state: source row pointer for next stage
    const float* src0 =
        x2 + ((size_t)b * 32 * 32 + (h + 2 * (wid + (k0 << 2)) - 20)) * 1024 + srcw;
    // producer: stage s -> pi_k = k0 + (s>>3), phase = s&7
    // src(s) = src0 + (s>>3)*8*1024 (pi step: +4 pi = +8 h2-rows... careful:
    //   pi step per k is +4 -> h2 step +8 rows -> +8*1024 floats)
    //   phase step: +CPH channel-rows = +CPH*32*1024 floats
    const unsigned dstb = smem_b +
        (unsigned)(32 * WT + wid * (NBUF * BUF_FLOATS) + lo) * 4u;

    auto do_stage = [&](int s) {
        if (lane == 0) {
            const int kk = s >> 3;
            const int ph = s & 7;
            const unsigned mb = mb_base + (unsigned)((s & 1) << 3);
            mbar_expect(mb, cpb * CPH);
            const float* src = src0 + (size_t)kk * (8 * 1024)
                                    + (size_t)ph * (CPH * 32 * 1024);
            const unsigned d = dstb + (unsigned)((s & 1) * (BUF_FLOATS * 4));
            #pragma unroll
            for (int r = 0; r < CPH; r++)
                bulk_g2s(d + (unsigned)r * (SLICE * 4u),
                         src + (size_t)r * 32 * 1024, cpb, mb);
        }
    };

    do_stage(0);

    for (int s = 0; s < total; s++) {
        if (s + 1 < total) do_stage(s + 1);

        mbar_wait(mb_base + (unsigned)((s & 1) << 3), (unsigned)((s >> 1) & 1));

        // ---- compute stage s: 4 channels ----
        const float* buf = x2b + (s & 1) * BUF_FLOATS;
        const int ph = s & 7;
        const float* x1p = x1base + ph * (CPH * WT);
        const float* xwp = buf + 8 * g + 20 * half;

        #pragma unroll 2
        for (int c = 0; c < CPH; c++) {
            const float* x1row = x1p + c * WT;
            const ulonglong2 A0 = *reinterpret_cast<const ulonglong2*>(x1row);
            const ulonglong2 A1 = *reinterpret_cast<const ulonglong2*>(x1row + 4);
            const unsigned long long a[4] = {A0.x, A0.y, A1.x, A1.y};

            ulonglong2 X[7];
            const float* bp = xwp + c * SLICE;
            #pragma unroll
            for (int j = 0; j < 7; j++)
                X[j] = *reinterpret_cast<const ulonglong2*>(bp + 4 * j);

            #pragma unroll
            for (int p = 0; p < 11; p++) {
                #pragma unroll
                for (int q = 0; q < 4; q++) {
                    const int k = p + q;                       // 0..13
                    const unsigned long long pk = (k & 1) ? X[k >> 1].y
                                                          : X[k >> 1].x;
                    acc[p][q] = ffma2(a[q], pk, acc[p][q]);
                }
            }
        }

        // ---- per-pi epilogue after last phase ----
        if ((s & 7) == 7) {
            const int pi = wid + ((k0 + (s >> 3)) << 2);
            #pragma unroll
            for (int p = 0; p < 11; p++) {
                if (!(half == 1 && p == 0)) {      // pj=10 dup by half A
                    const int pj = half ? (p + 10) : p;
                    float* op = out +
                        (((size_t)b * 441 + pi * 21 + pj) * 32 + h) * 1024 +
                        w0 + 8 * g;
                    float v[8];
                    #pragma unroll
                    for (int q = 0; q < 4; q++) {
                        float2 fv = *reinterpret_cast<float2*>(&acc[p][q]);
                        v[2 * q]     = fv.x * ((fv.x < 0.f) ? sn : sp);
                        v[2 * q + 1] = fv.y * ((fv.y < 0.f) ? sn : sp);
                    }
                    *reinterpret_cast<float4*>(op) =
                        make_float4(v[0], v[1], v[2], v[3]);
                    *reinterpret_cast<float4*>(op + 4) =
                        make_float4(v[4], v[5], v[6], v[7]);
                }
                #pragma unroll
                for (int q = 0; q < 4; q++) acc[p][q] = 0ull;
            }
        }
    }

    // ---- zero-store epilogue for out-of-range pi (h2 invalid -> out = 0) ----
    {
        const float4 z = make_float4(0.f, 0.f, 0.f, 0.f);
        for (int k = 0; k <= kmax; k++) {
            if (k >= k0 && k <= k1) continue;
            const int pi = wid + (k << 2);
            #pragma unroll
            for (int p = 0; p < 11; p++) {
                if (half == 1 && p == 0) continue;
                const int pj = half ? (p + 10) : p;
                float* op = out +
                    (((size_t)b * 441 + pi * 21 + pj) * 32 + h) * 1024 +
                    w0 + 8 * g;
                *reinterpret_cast<float4*>(op)     = z;
                *reinterpret_cast<float4*>(op + 4) = z;
            }
        }
    }
}

extern "C" void kernel_launch(void* const* d_in, const int* in_sizes, int n_in,
                              void* d_out, int out_size) {
    const float* x1 = (const float*)d_in[0];
    const float* x2 = (const float*)d_in[1];
    float* out = (float*)d_out;

    const size_t smem_bytes =
        (size_t)(32 * WT + 4 * NBUF * BUF_FLOATS) * sizeof(float) + 64;  // 37952 B
    cudaFuncSetAttribute(corr_kernel,
                         cudaFuncAttributeMaxDynamicSharedMemorySize,
                         (int)smem_bytes);

    dim3 grid(1024 / WT, 32, 4);   // (w-tiles, H, B)
    corr_kernel<<<grid, 128, smem_bytes>>>(x1, x2, out);
}

// round 15
// speedup vs baseline: 1.8841x; 1.0664x over previous
#include <cuda_runtime.h>

// out[b,pi,pj,h,w] = leaky_relu( (1/32) * sum_c x1[b,c,h,w] *
//                    x2_pad[b,c, h+2*pi-20, w+2*pj-20], 0.1 )
// B=4, C=32, H=32, W=1024, PATCH=21, DIL=2, PAD=20.
// Double-buffered bulk pipeline, sync-free stage loop, validity skip,
// LPT launch order: blockIdx.y -> h center-out (heaviest V(h) first) so the
// work-stealing tail wave consists of the lightest blocks.

#define WT      128
#define SLICE   168
#define CPH     4
#define NBUF    2
#define BUF_FLOATS (CPH * SLICE)   // 672

__device__ __forceinline__ unsigned long long ffma2(unsigned long long a,
                                                    unsigned long long b,
                                                    unsigned long long c) {
    unsigned long long d;
    asm("fma.rn.f32x2 %0, %1, %2, %3;" : "=l"(d) : "l"(a), "l"(b), "l"(c));
    return d;
}

__device__ __forceinline__ void mbar_init(unsigned mb) {
    asm volatile("mbarrier.init.shared.b64 [%0], 1;" :: "r"(mb) : "memory");
}
__device__ __forceinline__ void mbar_expect(unsigned mb, unsigned bytes) {
    asm volatile("mbarrier.arrive.expect_tx.shared.b64 _, [%0], %1;"
                 :: "r"(mb), "r"(bytes) : "memory");
}
__device__ __forceinline__ void bulk_g2s(unsigned dst, const void* src,
                                         unsigned bytes, unsigned mb) {
    asm volatile(
        "cp.async.bulk.shared::cta.global.mbarrier::complete_tx::bytes "
        "[%0], [%1], %2, [%3];"
        :: "r"(dst), "l"(src), "r"(bytes), "r"(mb) : "memory");
}
__device__ __forceinline__ void mbar_wait(unsigned mb, unsigned phase) {
    asm volatile(
        "{\n\t"
        ".reg .pred P;\n\t"
        "LAB_WAIT_%=:\n\t"
        "mbarrier.try_wait.parity.acquire.cta.shared::cta.b64 P, [%0], %1, 0x989680;\n\t"
        "@P bra.uni LAB_DONE_%=;\n\t"
        "bra.uni LAB_WAIT_%=;\n\t"
        "LAB_DONE_%=:\n\t"
        "}"
        :: "r"(mb), "r"(phase) : "memory");
}

extern __shared__ float smem[];

__global__ void __launch_bounds__(128, 4)
corr_kernel(const float* __restrict__ x1, const float* __restrict__ x2,
            float* __restrict__ out)
{
    const int w0   = blockIdx.x * WT;
    // LPT order: y walks h center-out (descending valid-pi count V(h))
    const int yy   = blockIdx.y;
    const int h    = (yy & 1) ? (16 + (yy >> 1)) : (15 - (yy >> 1));
    const int b    = blockIdx.z;
    const int tid  = threadIdx.x;
    const int wid  = tid >> 5;          // 4 warps
    const int lane = tid & 31;
    const int g    = lane >> 1;         // 16 w-groups of 8 w's
    const int half = lane & 1;          // 0: pj 0..10, 1: pj 10..20

    float* x1s = smem;                                       // [32][WT]
    float* x2b = smem + 32 * WT + wid * (NBUF * BUF_FLOATS);

    const unsigned smem_b  = (unsigned)__cvta_generic_to_shared(smem);
    const unsigned mb_base = smem_b +
        (unsigned)(32 * WT + 4 * NBUF * BUF_FLOATS) * 4u + (unsigned)wid * 16u;

    // ---- stage x1 tile: 32 channels x WT floats ----
    for (int f = tid; f < 32 * (WT / 4); f += 128) {
        const int c = f >> 5;
        const int j = f & 31;
        reinterpret_cast<float4*>(x1s)[f] = *reinterpret_cast<const float4*>(
            x1 + ((size_t)(b * 32 + c) * 32 + h) * 1024 + w0 + 4 * j);
    }
    __syncthreads();

    // per-block bulk-copy clipping (fixed for all stages)
    const int srcw = (w0 >= 20) ? (w0 - 20) : 0;
    const int lo   = (w0 >= 20) ? 0 : (20 - w0);
    const int hi   = (1044 - w0 < SLICE) ? (1044 - w0) : SLICE;
    const unsigned cpb = (unsigned)(hi - lo) * 4u;

    if (lane == 0) { mbar_init(mb_base); mbar_init(mb_base + 8); }
    if (lo > 0 || hi < SLICE) {                 // zero margins once
        const float4 z = make_float4(0.f, 0.f, 0.f, 0.f);
        for (int j = lane; j < NBUF * BUF_FLOATS / 4; j += 32)
            reinterpret_cast<float4*>(x2b)[j] = z;
    }
    __syncwarp();   // margins + mbarrier init visible warp-wide

    // valid pi range for this h: h2 = h + 2*pi - 20 in [0,32)
    const int pi_lo = (h >= 21) ? 0 : ((21 - h) >> 1);
    const int pi_hi = ((51 - h) >> 1) < 20 ? ((51 - h) >> 1) : 20;
    const int kmax = (20 - wid) >> 2;
    const int k0   = (pi_lo > wid) ? ((pi_lo - wid + 3) >> 2) : 0;
    const int k1   = (pi_hi - wid) >> 2;
    const int nval = k1 - k0 + 1;               // >= 2 always
    const int total = nval * 8;

    // acc[p][q]: pj = p + 10*half, w-pair q of this lane's 8 w's
    unsigned long long acc[11][4];
    #pragma unroll
    for (int p = 0; p < 11; p++)
        #pragma unroll
        for (int q = 0; q < 4; q++) acc[p][q] = 0ull;

    const float* x1base = x1s + 8 * g;
    const float sp = 0.03125f;    // 1/32
    const float sn = 0.003125f;   // 0.1/32

    // producer: stage s -> pi = wid + (k0 + (s>>3))*4, phase = s&7
    const float* src0 =
        x2 + ((size_t)b * 32 * 32 + (h + 2 * (wid + (k0 << 2)) - 20)) * 1024 + srcw;
    const unsigned dstb = smem_b +
        (unsigned)(32 * WT + wid * (NBUF * BUF_FLOATS) + lo) * 4u;

    auto do_stage = [&](int s) {
        if (lane == 0) {
            const int kk = s >> 3;
            const int ph = s & 7;
            const unsigned mb = mb_base + (unsigned)((s & 1) << 3);
            mbar_expect(mb, cpb * CPH);
            const float* src = src0 + (size_t)kk * (8 * 1024)
                                    + (size_t)ph * (CPH * 32 * 1024);
            const unsigned d = dstb + (unsigned)((s & 1) * (BUF_FLOATS * 4));
            #pragma unroll
            for (int r = 0; r < CPH; r++)
                bulk_g2s(d + (unsigned)r * (SLICE * 4u),
                         src + (size_t)r * 32 * 1024, cpb, mb);
        }
    };

    do_stage(0);

    for (int s = 0; s < total; s++) {
        if (s + 1 < total) do_stage(s + 1);

        mbar_wait(mb_base + (unsigned)((s & 1) << 3), (unsigned)((s >> 1) & 1));

        // ---- compute stage s: 4 channels ----
        const float* buf = x2b + (s & 1) * BUF_FLOATS;
        const int ph = s & 7;
        const float* x1p = x1base + ph * (CPH * WT);
        const float* xwp = buf + 8 * g + 20 * half;

        #pragma unroll 2
        for (int c = 0; c < CPH; c++) {
            const float* x1row = x1p + c * WT;
            const ulonglong2 A0 = *reinterpret_cast<const ulonglong2*>(x1row);
            const ulonglong2 A1 = *reinterpret_cast<const ulonglong2*>(x1row + 4);
            const unsigned long long a[4] = {A0.x, A0.y, A1.x, A1.y};

            ulonglong2 X[7];
            const float* bp = xwp + c * SLICE;
            #pragma unroll
            for (int j = 0; j < 7; j++)
                X[j] = *reinterpret_cast<const ulonglong2*>(bp + 4 * j);

            #pragma unroll
            for (int p = 0; p < 11; p++) {
                #pragma unroll
                for (int q = 0; q < 4; q++) {
                    const int k = p + q;                       // 0..13
                    const unsigned long long pk = (k & 1) ? X[k >> 1].y
                                                          : X[k >> 1].x;
                    acc[p][q] = ffma2(a[q], pk, acc[p][q]);
                }
            }
        }

        // ---- per-pi epilogue after last phase ----
        if ((s & 7) == 7) {
            const int pi = wid + ((k0 + (s >> 3)) << 2);
            #pragma unroll
            for (int p = 0; p < 11; p++) {
                if (!(half == 1 && p == 0)) {      // pj=10 dup by half A
                    const int pj = half ? (p + 10) : p;
                    float* op = out +
                        (((size_t)b * 441 + pi * 21 + pj) * 32 + h) * 1024 +
                        w0 + 8 * g;
                    float v[8];
                    #pragma unroll
                    for (int q = 0; q < 4; q++) {
                        float2 fv = *reinterpret_cast<float2*>(&acc[p][q]);
                        v[2 * q]     = fv.x * ((fv.x < 0.f) ? sn : sp);
                        v[2 * q + 1] = fv.y * ((fv.y < 0.f) ? sn : sp);
                    }
                    *reinterpret_cast<float4*>(op) =
                        make_float4(v[0], v[1], v[2], v[3]);
                    *reinterpret_cast<float4*>(op + 4) =
                        make_float4(v[4], v[5], v[6], v[7]);
                }
                #pragma unroll
                for (int q = 0; q < 4; q++) acc[p][q] = 0ull;
            }
        }
    }

    // ---- zero-store epilogue for out-of-range pi (h2 invalid -> out = 0) ----
    {
        const float4 z = make_float4(0.f, 0.f, 0.f, 0.f);
        for (int k = 0; k <= kmax; k++) {
            if (k >= k0 && k <= k1) continue;
            const int pi = wid + (k << 2);
            #pragma unroll
            for (int p = 0; p < 11; p++) {
                if (half == 1 && p == 0) continue;
                const int pj = half ? (p + 10) : p;
                float* op = out +
                    (((size_t)b * 441 + pi * 21 + pj) * 32 + h) * 1024 +
                    w0 + 8 * g;
                *reinterpret_cast<float4*>(op)     = z;
                *reinterpret_cast<float4*>(op + 4) = z;
            }
        }
    }
}

extern "C" void kernel_launch(void* const* d_in, const int* in_sizes, int n_in,
                              void* d_out, int out_size) {
    const float* x1 = (const float*)d_in[0];
    const float* x2 = (const float*)d_in[1];
    float* out = (float*)d_out;

    const size_t smem_bytes =
        (size_t)(32 * WT + 4 * NBUF * BUF_FLOATS) * sizeof(float) + 64;  // 37952 B
    cudaFuncSetAttribute(corr_kernel,
                         cudaFuncAttributeMaxDynamicSharedMemorySize,
                         (int)smem_bytes);

    dim3 grid(1024 / WT, 32, 4);   // (w-tiles, h-order, B)
    corr_kernel<<<grid, 128, smem_bytes>>>(x1, x2, out);
}

// round 16
// speedup vs baseline: 1.9210x; 1.0196x over previous
#include <cuda_runtime.h>
#include <cuda.h>

// out[b,pi,pj,h,w] = leaky_relu( (1/32) * sum_c x1[b,c,h,w] *
//                    x2_pad[b,c, h+2*pi-20, w+2*pj-20], 0.1 )
// B=4, C=32, H=32, W=1024, PATCH=21, DIL=2, PAD=20.
// R15 + single 3D-TMA staging per stage (UTMALDG, OOB zero-fill replaces all
// edge clipping). LPT launch order, validity skip, sync-free stage loop.

#define WT      128
#define SLICE   168
#define CPH     4
#define NBUF    2
#define BUF_FLOATS (CPH * SLICE)          // 672
#define TMA_BYTES  (SLICE * CPH * 4)      // 2688

__device__ __forceinline__ unsigned long long ffma2(unsigned long long a,
                                                    unsigned long long b,
                                                    unsigned long long c) {
    unsigned long long d;
    asm("fma.rn.f32x2 %0, %1, %2, %3;" : "=l"(d) : "l"(a), "l"(b), "l"(c));
    return d;
}

__device__ __forceinline__ void mbar_init(unsigned mb) {
    asm volatile("mbarrier.init.shared.b64 [%0], 1;" :: "r"(mb) : "memory");
}
__device__ __forceinline__ void mbar_expect(unsigned mb, unsigned bytes) {
    asm volatile("mbarrier.arrive.expect_tx.shared.b64 _, [%0], %1;"
                 :: "r"(mb), "r"(bytes) : "memory");
}
__device__ __forceinline__ void tma3d(unsigned dst, const CUtensorMap* m,
                                      int c0, int c1, int c2, unsigned mb) {
    asm volatile(
        "cp.async.bulk.tensor.3d.shared::cta.global.tile.mbarrier::complete_tx::bytes "
        "[%0], [%1, {%2, %3, %4}], [%5];"
        :: "r"(dst), "l"(m), "r"(c0), "r"(c1), "r"(c2), "r"(mb) : "memory");
}
__device__ __forceinline__ void mbar_wait(unsigned mb, unsigned phase) {
    asm volatile(
        "{\n\t"
        ".reg .pred P;\n\t"
        "LAB_WAIT_%=:\n\t"
        "mbarrier.try_wait.parity.acquire.cta.shared::cta.b64 P, [%0], %1, 0x989680;\n\t"
        "@P bra.uni LAB_DONE_%=;\n\t"
        "bra.uni LAB_WAIT_%=;\n\t"
        "LAB_DONE_%=:\n\t"
        "}"
        :: "r"(mb), "r"(phase) : "memory");
}

extern __shared__ float smem[];

__global__ void __launch_bounds__(128, 4)
corr_kernel(const float* __restrict__ x1, const float* __restrict__ x2,
            float* __restrict__ out, const __grid_constant__ CUtensorMap tmap)
{
    const int w0   = blockIdx.x * WT;
    // LPT order: y walks h center-out (descending valid-pi count V(h))
    const int yy   = blockIdx.y;
    const int h    = (yy & 1) ? (16 + (yy >> 1)) : (15 - (yy >> 1));
    const int b    = blockIdx.z;
    const int tid  = threadIdx.x;
    const int wid  = tid >> 5;          // 4 warps
    const int lane = tid & 31;
    const int g    = lane >> 1;         // 16 w-groups of 8 w's
    const int half = lane & 1;          // 0: pj 0..10, 1: pj 10..20

    float* x1s = smem;                                       // [32][WT]
    float* x2b = smem + 32 * WT + wid * (NBUF * BUF_FLOATS);

    const unsigned smem_b  = (unsigned)__cvta_generic_to_shared(smem);
    const unsigned mb_base = smem_b +
        (unsigned)(32 * WT + 4 * NBUF * BUF_FLOATS) * 4u + (unsigned)wid * 16u;

    // ---- stage x1 tile: 32 channels x WT floats ----
    for (int f = tid; f < 32 * (WT / 4); f += 128) {
        const int c = f >> 5;
        const int j = f & 31;
        reinterpret_cast<float4*>(x1s)[f] = *reinterpret_cast<const float4*>(
            x1 + ((size_t)(b * 32 + c) * 32 + h) * 1024 + w0 + 4 * j);
    }
    __syncthreads();

    if (lane == 0) { mbar_init(mb_base); mbar_init(mb_base + 8); }
    __syncwarp();   // mbarrier init visible warp-wide

    // valid pi range for this h: h2 = h + 2*pi - 20 in [0,32)
    const int pi_lo = (h >= 21) ? 0 : ((21 - h) >> 1);
    const int pi_hi = ((51 - h) >> 1) < 20 ? ((51 - h) >> 1) : 20;
    const int kmax = (20 - wid) >> 2;
    const int k0   = (pi_lo > wid) ? ((pi_lo - wid + 3) >> 2) : 0;
    const int k1   = (pi_hi - wid) >> 2;
    const int nval = k1 - k0 + 1;               // >= 2 always
    const int total = nval * 8;

    // acc[p][q]: pj = p + 10*half, w-pair q of this lane's 8 w's
    unsigned long long acc[11][4];
    #pragma unroll
    for (int p = 0; p < 11; p++)
        #pragma unroll
        for (int q = 0; q < 4; q++) acc[p][q] = 0ull;

    const float* x1base = x1s + 8 * g;
    const float sp = 0.03125f;    // 1/32
    const float sn = 0.003125f;   // 0.1/32

    // producer: stage s -> pi = wid + (k0 + (s>>3))*4, phase = s&7
    const int h2_0 = h + 2 * (wid + (k0 << 2)) - 20;   // h2 at k=k0 (valid)
    const int bc0  = b * 32;                           // dim2 base (b,c=0)
    const int wtm  = w0 - 20;                          // dim0 coord (may be <0)
    const unsigned dstb = smem_b +
        (unsigned)(32 * WT + wid * (NBUF * BUF_FLOATS)) * 4u;

    auto do_stage = [&](int s) {
        if (lane == 0) {
            const unsigned mb = mb_base + (unsigned)((s & 1) << 3);
            mbar_expect(mb, TMA_BYTES);
            tma3d(dstb + (unsigned)((s & 1) * (BUF_FLOATS * 4)), &tmap,
                  wtm, h2_0 + ((s >> 3) << 3), bc0 + ((s & 7) << 2), mb);
        }
    };

    do_stage(0);

    for (int s = 0; s < total; s++) {
        if (s + 1 < total) do_stage(s + 1);

        mbar_wait(mb_base + (unsigned)((s & 1) << 3), (unsigned)((s >> 1) & 1));

        // ---- compute stage s: 4 channels ----
        const float* buf = x2b + (s & 1) * BUF_FLOATS;
        const int ph = s & 7;
        const float* x1p = x1base + ph * (CPH * WT);
        const float* xwp = buf + 8 * g + 20 * half;

        #pragma unroll 2
        for (int c = 0; c < CPH; c++) {
            const float* x1row = x1p + c * WT;
            const ulonglong2 A0 = *reinterpret_cast<const ulonglong2*>(x1row);
            const ulonglong2 A1 = *reinterpret_cast<const ulonglong2*>(x1row + 4);
            const unsigned long long a[4] = {A0.x, A0.y, A1.x, A1.y};

            ulonglong2 X[7];
            const float* bp = xwp + c * SLICE;
            #pragma unroll
            for (int j = 0; j < 7; j++)
                X[j] = *reinterpret_cast<const ulonglong2*>(bp + 4 * j);

            #pragma unroll
            for (int p = 0; p < 11; p++) {
                #pragma unroll
                for (int q = 0; q < 4; q++) {
                    const int k = p + q;                       // 0..13
                    const unsigned long long pk = (k & 1) ? X[k >> 1].y
                                                          : X[k >> 1].x;
                    acc[p][q] = ffma2(a[q], pk, acc[p][q]);
                }
            }
        }

        // ---- per-pi epilogue after last phase ----
        if ((s & 7) == 7) {
            const int pi = wid + ((k0 + (s >> 3)) << 2);
            #pragma unroll
            for (int p = 0; p < 11; p++) {
                if (!(half == 1 && p == 0)) {      // pj=10 dup by half A
                    const int pj = half ? (p + 10) : p;
                    float* op = out +
                        (((size_t)b * 441 + pi * 21 + pj) * 32 + h) * 1024 +
                        w0 + 8 * g;
                    float v[8];
                    #pragma unroll
                    for (int q = 0; q < 4; q++) {
                        float2 fv = *reinterpret_cast<float2*>(&acc[p][q]);
                        v[2 * q]     = fv.x * ((fv.x < 0.f) ? sn : sp);
                        v[2 * q + 1] = fv.y * ((fv.y < 0.f) ? sn : sp);
                    }
                    *reinterpret_cast<float4*>(op) =
                        make_float4(v[0], v[1], v[2], v[3]);
                    *reinterpret_cast<float4*>(op + 4) =
                        make_float4(v[4], v[5], v[6], v[7]);
                }
                #pragma unroll
                for (int q = 0; q < 4; q++) acc[p][q] = 0ull;
            }
        }
    }

    // ---- zero-store epilogue for out-of-range pi (h2 invalid -> out = 0) ----
    {
        const float4 z = make_float4(0.f, 0.f, 0.f, 0.f);
        for (int k = 0; k <= kmax; k++) {
            if (k >= k0 && k <= k1) continue;
            const int pi = wid + (k << 2);
            #pragma unroll
            for (int p = 0; p < 11; p++) {
                if (half == 1 && p == 0) continue;
                const int pj = half ? (p + 10) : p;
                float* op = out +
                    (((size_t)b * 441 + pi * 21 + pj) * 32 + h) * 1024 +
                    w0 + 8 * g;
                *reinterpret_cast<float4*>(op)     = z;
                *reinterpret_cast<float4*>(op + 4) = z;
            }
        }
    }
}

typedef CUresult (*TMEncodeFn)(
    CUtensorMap*, CUtensorMapDataType, cuuint32_t, void*,
    const cuuint64_t*, const cuuint64_t*, const cuuint32_t*, const cuuint32_t*,
    CUtensorMapInterleave, CUtensorMapSwizzle, CUtensorMapL2promotion,
    CUtensorMapFloatOOBfill);

extern "C" void kernel_launch(void* const* d_in, const int* in_sizes, int n_in,
                              void* d_out, int out_size) {
    const float* x1 = (const float*)d_in[0];
    const float* x2 = (const float*)d_in[1];
    float* out = (float*)d_out;

    // Encode 3D tensor map for x2 viewed as [W=1024, H=32, B*C=128] f32.
    // Driver entry point fetched via the runtime (no -lcuda link needed).
    void* fn = nullptr;
    cudaDriverEntryPointQueryResult qr;
    cudaGetDriverEntryPoint("cuTensorMapEncodeTiled", &fn,
                            cudaEnableDefault, &qr);
    CUtensorMap tmap;
    cuuint64_t dims[3]    = {1024, 32, 128};
    cuuint64_t strides[2] = {1024ull * 4, 32ull * 1024 * 4};
    cuuint32_t box[3]     = {SLICE, 1, CPH};
    cuuint32_t es[3]      = {1, 1, 1};
    ((TMEncodeFn)fn)(&tmap, CU_TENSOR_MAP_DATA_TYPE_FLOAT32, 3, (void*)x2,
                     dims, strides, box, es,
                     CU_TENSOR_MAP_INTERLEAVE_NONE,
                     CU_TENSOR_MAP_SWIZZLE_NONE,
                     CU_TENSOR_MAP_L2_PROMOTION_L2_128B,
                     CU_TENSOR_MAP_FLOAT_OOB_FILL_NONE);

    const size_t smem_bytes =
        (size_t)(32 * WT + 4 * NBUF * BUF_FLOATS) * sizeof(float) + 64;  // 37952 B
    cudaFuncSetAttribute(corr_kernel,
                         cudaFuncAttributeMaxDynamicSharedMemorySize,
                         (int)smem_bytes);

    dim3 grid(1024 / WT, 32, 4);   // (w-tiles, h-order, B)
    corr_kernel<<<grid, 128, smem_bytes>>>(x1, x2, out, tmap);
}